// round 16
// baseline (speedup 1.0000x reference)
#include <cuda_runtime.h>
#include <cuda_fp16.h>
#include <cstdint>

// Problem constants
#define K_NODES 100000
#define K_RELS  500
#define K_MEM   512
#define K_IN    1024
#define K_BATCH 65536

// GEMM tiling (R13/R15 shape: CTA 128x128, 256 thr, 2 CTA/SM, fp16 BK=64)
#define BM 128
#define BN 128
#define BK 64
#define STR_H 72                      // halves/row (144 B) — ldmatrix conflict-free
#define A_TILE_H (BM * STR_H)
#define B_TILE_H (BN * STR_H)
#define STAGE_H (A_TILE_H + B_TILE_H)
#define STAGE_BYTES (STAGE_H * 2)     // 36864
#define NSTAGE 3
#define SMEM_BYTES (NSTAGE * STAGE_BYTES)   // 110592
#define NIT (K_IN / BK)               // 16 k-chunks

// Background-copy geometry (out = concat(ent,rel) * s), in float4 units
#define NENT4 12800000
#define Q4    12864000
#define BLK4  2048                    // float4 per stolen block (32 KB)
#define NBLK  6282                    // ceil(Q4 / BLK4)

// fp16 scratch for W: [2][512][1024] halves = 2 MB
__device__ uint32_t g_Wh[(size_t)2 * K_MEM * K_IN / 2];
// copy-overlap bookkeeping
__device__ int g_claim[256];
__device__ int g_work;
__device__ int g_bdone;

__device__ __forceinline__ int decode_time(const void* p) {
    int i = *(const int*)p;
    if (i < 0 || i > 1000000) i = (int)__int_as_float(i);
    return i;
}

// ---------------------------------------------------------------------------
// Kernel 0: convert W to fp16 + reset bookkeeping (runs before GEMM, in order)
// ---------------------------------------------------------------------------
__global__ void conv_w_kernel(const float* __restrict__ Wn,
                              const float* __restrict__ Wr) {
    if (blockIdx.x == 0 && blockIdx.y == 0) {
        g_claim[threadIdx.x] = 0;
        if (threadIdx.x == 0) { g_work = 0; g_bdone = 0; }
    }
    const size_t i = (size_t)blockIdx.x * blockDim.x + threadIdx.x;
    const float4 v = ((const float4*)(blockIdx.y ? Wr : Wn))[i];
    __half2 lo = __floats2half2_rn(v.x, v.y);
    __half2 hi = __floats2half2_rn(v.z, v.w);
    uint2 o;
    o.x = *(uint32_t*)&lo;
    o.y = *(uint32_t*)&hi;
    ((uint2*)(g_Wh + (size_t)blockIdx.y * K_MEM * K_IN / 2))[i] = o;
}

// ---------------------------------------------------------------------------
// Kernel 1: GEMM + bias + scale + scatter-add, with the memory-state copy
// (out = mem * s) folded in as work-stolen background blocks done by one
// resident "claimant" CTA per SM, overlapped with the MMA mainloop.
// ---------------------------------------------------------------------------
__device__ __forceinline__ void cp16(void* smem_dst, const void* gsrc) {
    uint32_t d = (uint32_t)__cvta_generic_to_shared(smem_dst);
    asm volatile("cp.async.cg.shared.global [%0], [%1], 16;" :: "r"(d), "l"(gsrc));
}
__device__ __forceinline__ void ldsm4(uint32_t& r0, uint32_t& r1,
                                      uint32_t& r2, uint32_t& r3, uint32_t a) {
    asm volatile("ldmatrix.sync.aligned.m8n8.x4.shared.b16 {%0,%1,%2,%3}, [%4];"
                 : "=r"(r0), "=r"(r1), "=r"(r2), "=r"(r3) : "r"(a));
}

__global__ __launch_bounds__(256, 2) void gemm_scatter_kernel(
    const float* __restrict__ Xn, const float* __restrict__ Xr,
    const float* __restrict__ ent, const float* __restrict__ rel,
    const float* __restrict__ bn, const float* __restrict__ br,
    const int* __restrict__ idn, const int* __restrict__ idr,
    const void* __restrict__ tp, float* __restrict__ out)
{
    extern __shared__ __half smem[];   // 3 stages of [A | B]
    __shared__ int sblk[2];
    __shared__ int sclaim;

    const int z = blockIdx.z;
    const float*    __restrict__ Xf  = z ? Xr : Xn;
    const uint32_t* __restrict__ Wh  = g_Wh + (size_t)z * K_MEM * K_IN / 2;
    const float*    __restrict__ bias = z ? br : bn;
    const int*      __restrict__ ids  = z ? idr : idn;
    const int obase = z ? K_NODES : 0;

    const int t = decode_time(tp);
    const float inv = 1.0f / (float)(t + 1);
    const float s = (t > 1) ? (float)t / (float)(t + 1) : 1.0f;

    const int bm    = blockIdx.y * BM;
    const int bnoff = blockIdx.x * BN;
    const int tid  = threadIdx.x;
    const int wid  = tid >> 5, lane = tid & 31;
    const int wm = (wid & 1) * 64;
    const int wn = (wid >> 1) * 32;
    const int grp = lane >> 2, tig = lane & 3;

    // Claim: first CTA to arrive on each SM becomes the copier (resident!)
    if (tid == 0) {
        uint32_t smid;
        asm("mov.u32 %0, %%smid;" : "=r"(smid));
        sclaim = (atomicExch(&g_claim[smid & 255], 1) == 0);
    }

    // ldmatrix per-lane offsets (bytes) — mapping validated in R6/R13
    const uint32_t aoff =
        ((((lane & 7) + ((lane >> 3) & 1) * 8) * STR_H) + ((lane >> 4) & 1) * 8) * 2;
    const uint32_t boff =
        ((((lane & 7) + ((lane >> 4) & 1) * 8) * STR_H) + ((lane >> 3) & 1) * 8) * 2;

    const uint32_t smem0 = (uint32_t)__cvta_generic_to_shared(smem);
    const uint32_t aBase0 = smem0 + (uint32_t)(wm * STR_H * 2) + aoff;
    const uint32_t bBase0 = smem0 + (uint32_t)(A_TILE_H * 2)
                          + (uint32_t)(wn * STR_H * 2) + boff;

    // --- Fill-side indexing ---
    const int r0  = tid >> 3;
    const int c8  = (tid & 7) * 8;
    const float* gA = Xf + (size_t)(bm + r0) * K_IN + c8;
    const char* gB = (const char*)Wh + ((size_t)(bnoff + r0) * K_IN + c8) * 2;
    const int sdstB = r0 * STR_H + c8;

    float4 v[2][2];

    auto ldgA2 = [&](int p) {
        #pragma unroll
        for (int j = 0; j < 2; ++j) {
            const float* sp = gA + (size_t)(2 * p + j) * 32 * K_IN;
            v[j][0] = __ldg((const float4*)sp);
            v[j][1] = __ldg((const float4*)(sp + 4));
        }
    };
    auto stsA2 = [&](int p, int st) {
        #pragma unroll
        for (int j = 0; j < 2; ++j) {
            __half2 h0 = __floats2half2_rn(v[j][0].x, v[j][0].y);
            __half2 h1 = __floats2half2_rn(v[j][0].z, v[j][0].w);
            __half2 h2 = __floats2half2_rn(v[j][1].x, v[j][1].y);
            __half2 h3 = __floats2half2_rn(v[j][1].z, v[j][1].w);
            uint4 u;
            u.x = *(uint32_t*)&h0; u.y = *(uint32_t*)&h1;
            u.z = *(uint32_t*)&h2; u.w = *(uint32_t*)&h3;
            *(uint4*)(smem + st * STAGE_H
                      + (r0 + (2 * p + j) * 32) * STR_H + c8) = u;
        }
    };
    auto fillB = [&](int st) {
        __half* dB = smem + st * STAGE_H + A_TILE_H + sdstB;
        #pragma unroll
        for (int i = 0; i < 4; i++)
            cp16(dB + i * 32 * STR_H, gB + (size_t)i * 32 * K_IN * 2);
        asm volatile("cp.async.commit_group;");
        gB += BK * 2;
    };
    // Background copy of one 32KB block of out = mem * s
    auto copyblk = [&](int b) {
        if (b < NBLK) {
            const int base = b * BLK4;
            const int end = (base + BLK4 < Q4) ? base + BLK4 : Q4;
            #pragma unroll 1
            for (int i = base + tid; i < end; i += 256) {
                float4 m = (i < NENT4) ? ((const float4*)ent)[i]
                                       : ((const float4*)rel)[i - NENT4];
                float4 o;
                o.x = m.x * s; o.y = m.y * s; o.z = m.z * s; o.w = m.w * s;
                ((float4*)out)[i] = o;
            }
        }
    };

    float acc[4][4][4] = {};

    // Prologue
    ldgA2(0); stsA2(0, 0); ldgA2(1); stsA2(1, 0); gA += BK;
    ldgA2(0); stsA2(0, 1); ldgA2(1); stsA2(1, 1); gA += BK;
    fillB(0); fillB(1);
    __syncthreads();               // sclaim visible
    const bool claimant = (sclaim != 0);
    int totBlk = 0;

    auto doks = [&](uint32_t aB, uint32_t bB, int ks) {
        uint32_t af[4][4], bf[4][2];
        #pragma unroll
        for (int mt = 0; mt < 4; ++mt)
            ldsm4(af[mt][0], af[mt][1], af[mt][2], af[mt][3],
                  aB + mt * (16 * STR_H * 2) + ks * 32);
        #pragma unroll
        for (int np = 0; np < 2; ++np) {
            uint32_t q0, q1, q2, q3;
            ldsm4(q0, q1, q2, q3, bB + np * (16 * STR_H * 2) + ks * 32);
            bf[2 * np][0] = q0; bf[2 * np][1] = q1;
            bf[2 * np + 1][0] = q2; bf[2 * np + 1][1] = q3;
        }
        #pragma unroll
        for (int mt = 0; mt < 4; ++mt)
            #pragma unroll
            for (int nt = 0; nt < 4; ++nt)
                asm volatile(
                    "mma.sync.aligned.m16n8k16.row.col.f32.f16.f16.f32 "
                    "{%0,%1,%2,%3}, {%4,%5,%6,%7}, {%8,%9}, {%0,%1,%2,%3};"
                    : "+f"(acc[mt][nt][0]), "+f"(acc[mt][nt][1]),
                      "+f"(acc[mt][nt][2]), "+f"(acc[mt][nt][3])
                    : "r"(af[mt][0]), "r"(af[mt][1]), "r"(af[mt][2]), "r"(af[mt][3]),
                      "r"(bf[nt][0]), "r"(bf[nt][1]));
    };

    for (int it = 0; it < NIT; ++it) {
        const int st = it % 3;
        if (claimant && tid == 0) sblk[it & 1] = atomicAdd(&g_work, 3);
        asm volatile("cp.async.wait_group 1;");
        __syncthreads();
        const int cbase = claimant ? sblk[it & 1] : NBLK;

        const int pst = (it + 2) % 3;
        const bool pf = (it + 2) < NIT;
        if (pf) fillB(pst);
        else asm volatile("cp.async.commit_group;");

        const uint32_t aB = aBase0 + st * STAGE_BYTES;
        const uint32_t bB = bBase0 + st * STAGE_BYTES;

        if (pf) ldgA2(0);
        if (claimant) { copyblk(cbase); totBlk += (cbase < NBLK); }
        doks(aB, bB, 0);
        doks(aB, bB, 1);
        if (pf) { stsA2(0, pst); ldgA2(1); gA += BK; }
        if (claimant) { copyblk(cbase + 1); totBlk += (cbase + 1 < NBLK); }
        doks(aB, bB, 2);
        if (claimant) { copyblk(cbase + 2); totBlk += (cbase + 2 < NBLK); }
        doks(aB, bB, 3);
        if (pf) stsA2(1, pst);
    }

    // Claimants publish completed copy blocks
    if (claimant) {
        __threadfence();
        __syncthreads();
        if (tid == 0) atomicAdd(&g_bdone, totBlk);
    }

    // All CTAs wait until the entire out initialization is complete
    if (tid == 0) {
        while (*(volatile int*)&g_bdone < NBLK) __nanosleep(64);
    }
    __syncthreads();
    __threadfence();

    // Epilogue: (acc + bias) * inv, scatter-add via float2 vector atomics
    float2 bv[4];
    #pragma unroll
    for (int nt = 0; nt < 4; ++nt) {
        int col = bnoff + wn + nt * 8 + tig * 2;
        bv[nt].x = bias[col];
        bv[nt].y = bias[col + 1];
    }
    #pragma unroll
    for (int mt = 0; mt < 4; ++mt) {
        #pragma unroll
        for (int h = 0; h < 2; ++h) {
            const int gb = bm + wm + mt * 16 + grp + h * 8;
            const long orow = (long)(ids[gb] + obase);
            float* dst = out + orow * K_MEM;
            #pragma unroll
            for (int nt = 0; nt < 4; ++nt) {
                const int col = bnoff + wn + nt * 8 + tig * 2;
                float2 w;
                w.x = (acc[mt][nt][h * 2 + 0] + bv[nt].x) * inv;
                w.y = (acc[mt][nt][h * 2 + 1] + bv[nt].y) * inv;
                atomicAdd((float2*)(dst + col), w);
            }
        }
    }
}

// ---------------------------------------------------------------------------
extern "C" void kernel_launch(void* const* d_in, const int* in_sizes, int n_in,
                              void* d_out, int out_size) {
    const float* Xn  = (const float*)d_in[0];
    const float* Xr  = (const float*)d_in[1];
    const int*   idn = (const int*)  d_in[2];
    const int*   idr = (const int*)  d_in[3];
    const float* ent = (const float*)d_in[4];
    const float* rel = (const float*)d_in[5];
    const float* Wn  = (const float*)d_in[6];
    const float* bn  = (const float*)d_in[7];
    const float* Wr  = (const float*)d_in[8];
    const float* br  = (const float*)d_in[9];
    const void*  tp  = d_in[10];
    float* out = (float*)d_out;

    // 0) W -> fp16 scratch + reset claim/work counters
    conv_w_kernel<<<dim3(K_MEM * (K_IN / 4) / 256, 2), 256>>>(Wn, Wr);

    // 1) GEMM + scatter-add with fused background out-initialization
    cudaFuncSetAttribute(gemm_scatter_kernel,
                         cudaFuncAttributeMaxDynamicSharedMemorySize, SMEM_BYTES);
    dim3 grid(K_MEM / BN, K_BATCH / BM, 2);
    gemm_scatter_kernel<<<grid, 256, SMEM_BYTES>>>(
        Xn, Xr, ent, rel, bn, br, idn, idr, tp, out);
}